// round 3
// baseline (speedup 1.0000x reference)
#include <cuda_runtime.h>
#include <cstdint>

// Problem constants
#define B_       8192
#define NROW     40
#define FDIM     256
#define NF       (NROW*FDIM)        // 10240
#define TOTROWS  (B_*NROW)          // 327680
#define TOTELEM  ((size_t)TOTROWS*FDIM)  // 83,886,080
#define EPS_     1e-5f

// Scratch (device-static: no allocations allowed)
__device__ float g_z[TOTELEM];      // (adj_blk @ inp), pre-rounded to tf32
__device__ float g_y[TOTELEM];      // Z @ W
__device__ float g_Wt[FDIM*FDIM];   // W rounded to tf32
__device__ float g_sum[NF];
__device__ float g_sq[NF];
__device__ float g_scale[NF];
__device__ float g_shift[NF];

__device__ __forceinline__ float to_tf32(float x){
    float r;
    asm("cvt.rna.tf32.f32 %0, %1;" : "=f"(r) : "f"(x));
    return r;
}

__device__ __forceinline__ void cpa16(void* smem_dst, const void* gsrc){
    unsigned d = (unsigned)__cvta_generic_to_shared(smem_dst);
    asm volatile("cp.async.cg.shared.global [%0], [%1], 16;" :: "r"(d), "l"(gsrc));
}

__device__ __forceinline__ void mma_tf32(float* c, const unsigned* a, const unsigned* b){
    asm volatile(
        "mma.sync.aligned.m16n8k8.row.col.f32.tf32.tf32.f32 "
        "{%0,%1,%2,%3}, {%4,%5,%6,%7}, {%8,%9}, {%0,%1,%2,%3};\n"
        : "+f"(c[0]), "+f"(c[1]), "+f"(c[2]), "+f"(c[3])
        : "r"(a[0]), "r"(a[1]), "r"(a[2]), "r"(a[3]), "r"(b[0]), "r"(b[1]));
}

// ---------------------------------------------------------------------------
// K0: convert W to tf32, zero stat accumulators (must rezero every launch —
// graph replays).
__global__ void k_prep(const float* __restrict__ W){
    int i = blockIdx.x * 256 + threadIdx.x;
    if (i < FDIM*FDIM) g_Wt[i] = to_tf32(W[i]);
    if (i < NF){ g_sum[i] = 0.f; g_sq[i] = 0.f; }
}

// ---------------------------------------------------------------------------
// K1: z[b,r,f] = sum_{j in block(r)} adj[b,r,j] * inp[b,j,f], rounded to tf32.
// Each CTA handles 2 batches; each thread a float2 column pair.
__global__ __launch_bounds__(256) void k_z(const float* __restrict__ inp,
                                           const float* __restrict__ adj){
    int b2  = blockIdx.x;            // 4096 CTAs
    int sub = threadIdx.x >> 7;      // which of 2 batches
    int fc  = threadIdx.x & 127;     // float2 column index (0..127)
    int b   = b2*2 + sub;

    __shared__ float sadj[2][NROW][NROW];
    for (int i = threadIdx.x; i < 2*NROW*NROW; i += 256){
        int bb = i / (NROW*NROW);
        int j  = i % (NROW*NROW);
        sadj[bb][j/NROW][j%NROW] = adj[(size_t)(b2*2+bb)*NROW*NROW + j];
    }
    __syncthreads();

    float2 x[NROW];
    const float2* ip = (const float2*)inp + (size_t)b*NROW*128 + fc;
    #pragma unroll
    for (int j = 0; j < NROW; j++) x[j] = ip[(size_t)j*128];

    float2* zp = (float2*)g_z + (size_t)b*NROW*128 + fc;
    #pragma unroll
    for (int r = 0; r < NROW; r++){
        int s = (r/10)*10;
        float2 acc = make_float2(0.f, 0.f);
        #pragma unroll
        for (int j = 0; j < 10; j++){
            float av = sadj[sub][r][s+j];
            acc.x += av * x[s+j].x;
            acc.y += av * x[s+j].y;
        }
        float2 o; o.x = to_tf32(acc.x); o.y = to_tf32(acc.y);
        zp[(size_t)r*128] = o;
    }
}

// ---------------------------------------------------------------------------
// K2: Y = Z @ W  (tf32 mma.sync). CTA tile 128x128, K-tile 16, double-buffered
// cp.async. 256 threads = 8 warps as 4(m) x 2(n); warp tile 32x64.
#define KT 16
#define NSTAGE (FDIM/KT)   // 16

__global__ __launch_bounds__(256) void k_gemm(){
    __shared__ float sA[2][128][20];   // pad 20: conflict-free A lds
    __shared__ float sB[2][KT][136];   // pad 136: conflict-free B lds

    int tid  = threadIdx.x;
    size_t rowbase = (size_t)blockIdx.x * 128;
    int n0   = blockIdx.y * 128;
    int lane = tid & 31, warp = tid >> 5;
    int wm   = warp >> 1, wn = warp & 1;
    int g    = lane >> 2, t = lane & 3;

    // gmem->smem load mapping
    int la_row = tid >> 2;            // 0..63 (+64)
    int la_col = (tid & 3) * 4;       // 0,4,8,12
    int lb_row = tid >> 5;            // 0..7 (+8)
    int lb_col = (tid & 31) * 4;      // 0..124

    float acc[2][8][4];
    #pragma unroll
    for (int mt = 0; mt < 2; mt++)
        #pragma unroll
        for (int nt = 0; nt < 8; nt++)
            #pragma unroll
            for (int v = 0; v < 4; v++) acc[mt][nt][v] = 0.f;

    auto loadStage = [&](int s, int buf){
        int k0 = s * KT;
        cpa16(&sA[buf][la_row   ][la_col], g_z + (rowbase + la_row     )*FDIM + k0 + la_col);
        cpa16(&sA[buf][la_row+64][la_col], g_z + (rowbase + la_row + 64)*FDIM + k0 + la_col);
        cpa16(&sB[buf][lb_row   ][lb_col], g_Wt + (size_t)(k0 + lb_row    )*FDIM + n0 + lb_col);
        cpa16(&sB[buf][lb_row+8 ][lb_col], g_Wt + (size_t)(k0 + lb_row + 8)*FDIM + n0 + lb_col);
    };

    loadStage(0, 0);
    asm volatile("cp.async.commit_group;");

    for (int s = 0; s < NSTAGE; s++){
        int cur = s & 1;
        asm volatile("cp.async.wait_all;" ::: "memory");
        __syncthreads();
        if (s + 1 < NSTAGE){
            loadStage(s + 1, cur ^ 1);
            asm volatile("cp.async.commit_group;");
        }
        #pragma unroll
        for (int k8 = 0; k8 < KT/8; k8++){
            unsigned a[2][4], bf[8][2];
            int kc = k8*8 + t;
            #pragma unroll
            for (int mt = 0; mt < 2; mt++){
                int r0 = wm*32 + mt*16 + g;
                a[mt][0] = __float_as_uint(sA[cur][r0  ][kc  ]);
                a[mt][1] = __float_as_uint(sA[cur][r0+8][kc  ]);
                a[mt][2] = __float_as_uint(sA[cur][r0  ][kc+4]);
                a[mt][3] = __float_as_uint(sA[cur][r0+8][kc+4]);
            }
            #pragma unroll
            for (int nt = 0; nt < 8; nt++){
                int cc = wn*64 + nt*8 + g;
                bf[nt][0] = __float_as_uint(sB[cur][kc  ][cc]);
                bf[nt][1] = __float_as_uint(sB[cur][kc+4][cc]);
            }
            #pragma unroll
            for (int mt = 0; mt < 2; mt++)
                #pragma unroll
                for (int nt = 0; nt < 8; nt++)
                    mma_tf32(acc[mt][nt], a[mt], bf[nt]);
        }
        __syncthreads();
    }

    // Epilogue: write Y (float2 stores, 32B-sector coalesced)
    #pragma unroll
    for (int mt = 0; mt < 2; mt++){
        int r = wm*32 + mt*16 + g;
        #pragma unroll
        for (int nt = 0; nt < 8; nt++){
            int c = n0 + wn*64 + nt*8 + 2*t;
            float2 v0 = make_float2(acc[mt][nt][0], acc[mt][nt][1]);
            float2 v1 = make_float2(acc[mt][nt][2], acc[mt][nt][3]);
            *(float2*)(g_y + (rowbase + r    )*FDIM + c) = v0;
            *(float2*)(g_y + (rowbase + r + 8)*FDIM + c) = v1;
        }
    }
}

// ---------------------------------------------------------------------------
// K3: per-feature (r,f) sum / sumsq over the batch dim.
__global__ __launch_bounds__(256) void k_stat(){
    int r = blockIdx.x;        // 40
    int chunk = blockIdx.y;    // 64 chunks of 128 batches
    int f = threadIdx.x;       // 256
    const float* p = g_y + (size_t)chunk*128*NF + (size_t)r*FDIM + f;
    float s = 0.f, s2 = 0.f;
    #pragma unroll 4
    for (int b = 0; b < 128; b++){
        float v = p[(size_t)b*NF];
        s += v; s2 += v*v;
    }
    atomicAdd(&g_sum[r*FDIM + f], s);
    atomicAdd(&g_sq [r*FDIM + f], s2);
}

// ---------------------------------------------------------------------------
// K4: fold mean/var/gamma/beta into per-feature scale & shift.
// out = (y - mean)*rsqrt(var+eps)*gamma[r/10] + sum_i beta[i]
//     = y*scale + (betaSum - mean*scale)
__global__ void k_final(const float* __restrict__ gamma,
                        const float* __restrict__ beta){
    int q = blockIdx.x * 256 + threadIdx.x;   // 0..10239
    float inv = 1.f / (float)B_;
    float mean = g_sum[q] * inv;
    float var  = g_sq[q] * inv - mean*mean;
    int i = q / (10*FDIM);                     // block owning row r = q/256
    float sc = rsqrtf(var + EPS_) * gamma[i*NF + q];
    float bs = beta[q] + beta[NF + q] + beta[2*NF + q] + beta[3*NF + q];
    g_scale[q] = sc;
    g_shift[q] = bs - mean*sc;
}

// ---------------------------------------------------------------------------
// K5: streaming normalize (float4).
__global__ __launch_bounds__(256) void k_norm(float* __restrict__ out){
    size_t idx = (size_t)blockIdx.x * 256 + threadIdx.x;  // < 20,971,520
    int q4 = (int)(idx % (NF/4));
    float4 v  = ((const float4*)g_y)[idx];
    float4 sc = ((const float4*)g_scale)[q4];
    float4 sh = ((const float4*)g_shift)[q4];
    float4 o;
    o.x = v.x*sc.x + sh.x;
    o.y = v.y*sc.y + sh.y;
    o.z = v.z*sc.z + sh.z;
    o.w = v.w*sc.w + sh.w;
    ((float4*)out)[idx] = o;
}

// ---------------------------------------------------------------------------
extern "C" void kernel_launch(void* const* d_in, const int* in_sizes, int n_in,
                              void* d_out, int out_size){
    const float* inp   = (const float*)d_in[0];
    const float* adj   = (const float*)d_in[1];
    const float* W     = (const float*)d_in[2];
    const float* gamma = (const float*)d_in[3];
    const float* beta  = (const float*)d_in[4];
    float* out = (float*)d_out;

    k_prep<<<256, 256>>>(W);
    k_z   <<<B_/2, 256>>>(inp, adj);
    k_gemm<<<dim3(TOTROWS/128, FDIM/128), 256>>>();
    k_stat<<<dim3(NROW, 64), 256>>>();
    k_final<<<NF/256, 256>>>(gamma, beta);
    k_norm<<<(unsigned)(TOTELEM/4/256), 256>>>(out);
}